// round 1
// baseline (speedup 1.0000x reference)
#include <cuda_runtime.h>
#include <cuda_bf16.h>
#include <math.h>
#include <stdint.h>

// MultiResolutionHashGrid: N=1e6 points, L=16 levels, T=2^19 entries, F=2 feats.
// One thread per point. 8 float2 gathers per level (L2-resident 64MB table),
// trilinear interpolation, float2 store per level.

#define L_LEVELS 16
#define T_SIZE   524288u          // 2^19
#define T_MASK   (T_SIZE - 1u)
#define P1 2654435761u
#define P2 805459861u

struct ResArr { float r[L_LEVELS]; };

__global__ __launch_bounds__(256)
void hashgrid_kernel(const float* __restrict__ pos,
                     const float* __restrict__ table,
                     float* __restrict__ out,
                     int N, ResArr res)
{
    int n = blockIdx.x * blockDim.x + threadIdx.x;
    if (n >= N) return;

    const float HI = 1.0f - 1e-6f;
    float px = pos[3 * n + 0];
    float py = pos[3 * n + 1];
    float pz = pos[3 * n + 2];
    // normalized = clip((p - (-1)) / 2.0, 0, 1-1e-6)   (2+1e-8 rounds to 2.0f)
    float nx = fminf(fmaxf((px + 1.0f) * 0.5f, 0.0f), HI);
    float ny = fminf(fmaxf((py + 1.0f) * 0.5f, 0.0f), HI);
    float nz = fminf(fmaxf((pz + 1.0f) * 0.5f, 0.0f), HI);

    float2* out2 = reinterpret_cast<float2*>(out) + (size_t)n * L_LEVELS;
    const float2* tbl2 = reinterpret_cast<const float2*>(table);

    #pragma unroll
    for (int l = 0; l < L_LEVELS; ++l) {
        float rr = res.r[l];
        float sx = nx * rr, sy = ny * rr, sz = nz * rr;
        float fx0 = floorf(sx), fy0 = floorf(sy), fz0 = floorf(sz);
        float fx = sx - fx0, fy = sy - fy0, fz = sz - fz0;

        uint32_t cx = (uint32_t)(int32_t)fx0;
        uint32_t cy = (uint32_t)(int32_t)fy0;
        uint32_t cz = (uint32_t)(int32_t)fz0;

        uint32_t x0 = cx;            // prime 1
        uint32_t x1 = cx + 1u;
        uint32_t y0 = cy * P1;
        uint32_t y1 = y0 + P1;
        uint32_t z0 = cz * P2;
        uint32_t z1 = z0 + P2;

        const float2* t = tbl2 + (size_t)l * T_SIZE;
        // corner order matches reference offsets:
        // [0,0,0],[0,0,1],[0,1,0],[0,1,1],[1,0,0],[1,0,1],[1,1,0],[1,1,1]
        float2 f000 = __ldg(&t[(x0 ^ y0 ^ z0) & T_MASK]);
        float2 f001 = __ldg(&t[(x0 ^ y0 ^ z1) & T_MASK]);
        float2 f010 = __ldg(&t[(x0 ^ y1 ^ z0) & T_MASK]);
        float2 f011 = __ldg(&t[(x0 ^ y1 ^ z1) & T_MASK]);
        float2 f100 = __ldg(&t[(x1 ^ y0 ^ z0) & T_MASK]);
        float2 f101 = __ldg(&t[(x1 ^ y0 ^ z1) & T_MASK]);
        float2 f110 = __ldg(&t[(x1 ^ y1 ^ z0) & T_MASK]);
        float2 f111 = __ldg(&t[(x1 ^ y1 ^ z1) & T_MASK]);

        float omz = 1.0f - fz;
        float c00x = f000.x * omz + f001.x * fz;
        float c00y = f000.y * omz + f001.y * fz;
        float c01x = f010.x * omz + f011.x * fz;
        float c01y = f010.y * omz + f011.y * fz;
        float c10x = f100.x * omz + f101.x * fz;
        float c10y = f100.y * omz + f101.y * fz;
        float c11x = f110.x * omz + f111.x * fz;
        float c11y = f110.y * omz + f111.y * fz;

        float omy = 1.0f - fy;
        float c0x = c00x * omy + c01x * fy;
        float c0y = c00y * omy + c01y * fy;
        float c1x = c10x * omy + c11x * fy;
        float c1y = c10y * omy + c11y * fy;

        float omx = 1.0f - fx;
        float2 o;
        o.x = c0x * omx + c1x * fx;
        o.y = c0y * omx + c1y * fx;
        out2[l] = o;
    }
}

extern "C" void kernel_launch(void* const* d_in, const int* in_sizes, int n_in,
                              void* d_out, int out_size)
{
    const float* positions   = (const float*)d_in[0];   // (N, 3)
    const float* hash_tables = (const float*)d_in[1];   // (L, T, F)
    float* out = (float*)d_out;                         // (N, L*F)

    int N = in_sizes[0] / 3;

    // Compute resolutions with the SAME double-precision libm sequence as the
    // Python reference: GROWTH = exp((log(2048)-log(16))/15); ceil(16*GROWTH**l).
    ResArr res;
    double growth = exp((log(2048.0) - log(16.0)) / 15.0);
    for (int l = 0; l < L_LEVELS; ++l) {
        res.r[l] = (float)ceil(16.0 * pow(growth, (double)l));
    }

    int threads = 256;
    int blocks = (N + threads - 1) / threads;
    hashgrid_kernel<<<blocks, threads>>>(positions, hash_tables, out, N, res);
}